// round 1
// baseline (speedup 1.0000x reference)
#include <cuda_runtime.h>
#include <cstdint>

// Deformable conv2d: B=2, CIN=64, H=128, W=256, COUT=64, K=3, stride=1, pad=1, dil=1
#define B_N   2
#define C_IN  64
#define H_IN  128
#define W_IN  256
#define C_OUT 64
#define KK    9
#define H_O   128
#define W_O   256
#define HW    (H_IN * W_IN)     // 32768
#define HWO   (H_O * W_O)       // 32768
#define NPIX  (B_N * HWO)       // 65536
#define TPB   256

// ---- packed f32x2 helpers (sm_103a) ----
__device__ __forceinline__ unsigned long long pack2(float lo, float hi) {
    unsigned long long r;
    asm("mov.b64 %0, {%1, %2};" : "=l"(r) : "f"(lo), "f"(hi));
    return r;
}
__device__ __forceinline__ void unpack2(unsigned long long v, float& lo, float& hi) {
    asm("mov.b64 {%0, %1}, %2;" : "=f"(lo), "=f"(hi) : "l"(v));
}
__device__ __forceinline__ unsigned long long fma2(unsigned long long a,
                                                   unsigned long long b,
                                                   unsigned long long c) {
    unsigned long long d;
    asm("fma.rn.f32x2 %0, %1, %2, %3;" : "=l"(d) : "l"(a), "l"(b), "l"(c));
    return d;
}

__global__ __launch_bounds__(TPB, 2)
void deform_conv2d_kernel(const float* __restrict__ x,
                          const float* __restrict__ offset,
                          const float* __restrict__ weight,
                          const float* __restrict__ bias,
                          float* __restrict__ out) {
    // weight slice for current k, laid out [cin][cout] so cout is contiguous
    __shared__ float w_s[C_IN * C_OUT];   // 16 KB

    const int tid = threadIdx.x;
    const int p   = blockIdx.x * TPB + tid;   // grid sized exactly, no bounds check
    const int b   = p / HWO;
    const int rem = p - b * HWO;
    const int ho  = rem / W_O;
    const int wo  = rem - ho * W_O;

    // 64 cout accumulators as 32 packed f32x2, initialized with bias
    unsigned long long acc[32];
#pragma unroll
    for (int j = 0; j < 32; j++) acc[j] = pack2(bias[2 * j], bias[2 * j + 1]);

    const float* xb   = x + (size_t)b * C_IN * HW;
    const float* offb = offset + (size_t)b * 2 * KK * HWO + rem;

    for (int k = 0; k < KK; k++) {
        // stage this k's weight slice: w_s[cin*64 + cout] = weight[cout][cin][k]
        __syncthreads();   // previous iteration's readers done
#pragma unroll
        for (int i = tid; i < C_IN * C_OUT; i += TPB) {
            int cin  = i >> 6;
            int cout = i & 63;
            w_s[i] = weight[(cout * C_IN + cin) * KK + k];
        }
        __syncthreads();

        // bilinear sampling params for (pixel, k) — shared across all cin
        const float offy = offb[(2 * k + 0) * HWO];
        const float offx = offb[(2 * k + 1) * HWO];
        const float py = (float)(ho - 1 + k / 3) + offy;
        const float px = (float)(wo - 1 + k % 3) + offx;
        const float y0f = floorf(py);
        const float x0f = floorf(px);
        const int   y0  = (int)y0f;
        const int   x0  = (int)x0f;
        const float wy  = py - y0f;
        const float wx  = px - x0f;
        const int   y1  = y0 + 1;
        const int   x1  = x0 + 1;
        const bool vy0 = (y0 >= 0) && (y0 < H_IN);
        const bool vy1 = (y1 >= 0) && (y1 < H_IN);
        const bool vx0 = (x0 >= 0) && (x0 < W_IN);
        const bool vx1 = (x1 >= 0) && (x1 < W_IN);
        const int cy0 = min(max(y0, 0), H_IN - 1);
        const int cy1 = min(max(y1, 0), H_IN - 1);
        const int cx0 = min(max(x0, 0), W_IN - 1);
        const int cx1 = min(max(x1, 0), W_IN - 1);
        const int i00 = cy0 * W_IN + cx0;
        const int i01 = cy0 * W_IN + cx1;
        const int i10 = cy1 * W_IN + cx0;
        const int i11 = cy1 * W_IN + cx1;
        const float a00 = (vy0 && vx0) ? (1.0f - wy) * (1.0f - wx) : 0.0f;
        const float a01 = (vy0 && vx1) ? (1.0f - wy) * wx          : 0.0f;
        const float a10 = (vy1 && vx0) ? wy * (1.0f - wx)          : 0.0f;
        const float a11 = (vy1 && vx1) ? wy * wx                   : 0.0f;

        const float* xc = xb;
#pragma unroll 2
        for (int cin = 0; cin < C_IN; cin++) {
            const float v00 = __ldg(xc + i00);
            const float v01 = __ldg(xc + i01);
            const float v10 = __ldg(xc + i10);
            const float v11 = __ldg(xc + i11);
            xc += HW;
            const float s = v00 * a00 + v01 * a01 + v10 * a10 + v11 * a11;
            const unsigned long long s2 = pack2(s, s);
            const unsigned long long* wrow =
                reinterpret_cast<const unsigned long long*>(w_s + (cin << 6));
#pragma unroll
            for (int j = 0; j < 32; j++) acc[j] = fma2(s2, wrow[j], acc[j]);
        }
    }

    // out[b][cout][ho][wo]
    float* ob = out + (size_t)b * C_OUT * HWO + rem;
#pragma unroll
    for (int j = 0; j < 32; j++) {
        float lo, hi;
        unpack2(acc[j], lo, hi);
        ob[(size_t)(2 * j)     * HWO] = lo;
        ob[(size_t)(2 * j + 1) * HWO] = hi;
    }
}

extern "C" void kernel_launch(void* const* d_in, const int* in_sizes, int n_in,
                              void* d_out, int out_size) {
    const float* x      = (const float*)d_in[0];
    const float* offset = (const float*)d_in[1];
    const float* weight = (const float*)d_in[2];
    const float* bias   = (const float*)d_in[3];
    float* out = (float*)d_out;
    (void)in_sizes; (void)n_in; (void)out_size;

    deform_conv2d_kernel<<<NPIX / TPB, TPB>>>(x, offset, weight, bias, out);
}

// round 2
// speedup vs baseline: 1.6505x; 1.6505x over previous
#include <cuda_runtime.h>
#include <cstdint>

// Deformable conv2d: B=2, CIN=64, H=128, W=256, COUT=64, K=3, s=1, p=1, d=1
#define B_N   2
#define C_IN  64
#define H_IN  128
#define W_IN  256
#define C_OUT 64
#define KK    9
#define H_O   128
#define W_O   256
#define HW    (H_IN * W_IN)     // 32768
#define HWO   (H_O * W_O)       // 32768
#define NPIX  (B_N * HWO)       // 65536

#define TPX   128               // pixels per block (half a row)
#define TPB   256
#define SROW  68                // S row stride in floats (64 + 4 pad)

// dynamic smem layout (floats):
//   S   : TPX * SROW            = 8704
//   Wsh : 64 * 64               = 4096
//   Pi  : 4 * TPX (ints)        = 512
//   Pa  : 4 * TPX               = 512
#define SMEM_FLOATS (TPX * SROW + 4096 + 4 * TPX + 4 * TPX)
#define SMEM_BYTES  (SMEM_FLOATS * 4)

typedef unsigned long long u64;

__device__ float g_xt[(size_t)B_N * HW * C_IN];   // NHWC scratch, 16 MB
__device__ float g_wt[KK * C_IN * C_OUT];         // [k][cin][cout], 144 KB

__device__ __forceinline__ u64 pack2(float lo, float hi) {
    u64 r;
    asm("mov.b64 %0, {%1, %2};" : "=l"(r) : "f"(lo), "f"(hi));
    return r;
}
__device__ __forceinline__ void unpack2(u64 v, float& lo, float& hi) {
    asm("mov.b64 {%0, %1}, %2;" : "=f"(lo), "=f"(hi) : "l"(v));
}
__device__ __forceinline__ u64 fma2(u64 a, u64 b, u64 c) {
    u64 d;
    asm("fma.rn.f32x2 %0, %1, %2, %3;" : "=l"(d) : "l"(a), "l"(b), "l"(c));
    return d;
}

// ---- NCHW -> NHWC transpose (treat as [C, HW] -> [HW, C] per batch) ----
__global__ void transpose_nchw_nhwc(const float* __restrict__ x) {
    __shared__ float tile[32][33];
    const int b   = blockIdx.z;
    const int c0  = blockIdx.y * 32;
    const int hw0 = blockIdx.x * 32;
    const int tx  = threadIdx.x;
    const int ty  = threadIdx.y;   // block (32, 8)
    const float* xb = x + (size_t)b * C_IN * HW;
    float* xtb = g_xt + (size_t)b * HW * C_IN;
#pragma unroll
    for (int j = 0; j < 32; j += 8)
        tile[ty + j][tx] = xb[(size_t)(c0 + ty + j) * HW + hw0 + tx];
    __syncthreads();
#pragma unroll
    for (int j = 0; j < 32; j += 8)
        xtb[(size_t)(hw0 + ty + j) * C_IN + c0 + tx] = tile[tx][ty + j];
}

// ---- weight [cout][cin][k] -> [k][cin][cout] ----
__global__ void transpose_weight(const float* __restrict__ weight) {
    int i = blockIdx.x * 256 + threadIdx.x;
    if (i < KK * C_IN * C_OUT) {
        int k    = i / (C_IN * C_OUT);
        int r    = i - k * (C_IN * C_OUT);
        int cin  = r >> 6;
        int cout = r & 63;
        g_wt[i] = weight[(cout * C_IN + cin) * KK + k];
    }
}

// ---- main kernel: per-k im2col tile in smem + register-blocked GEMM ----
__global__ __launch_bounds__(TPB, 3)
void deform_main(const float* __restrict__ offset,
                 const float* __restrict__ bias,
                 float* __restrict__ out) {
    extern __shared__ float sm[];
    float* S   = sm;                              // [TPX][SROW]
    float* Wsh = sm + TPX * SROW;                 // [64][64] (cin-major, cout contig)
    int*   Pi  = (int*)(Wsh + 4096);              // [4][TPX] corner indices
    float* Pa  = (float*)(Pi + 4 * TPX);          // [4][TPX] corner weights

    const int tid = threadIdx.x;
    const int p0  = blockIdx.x * TPX;
    const int b   = p0 >> 15;           // / HWO
    const int rem = p0 & (HWO - 1);
    const int ho  = rem >> 8;           // / W_O
    const int wo0 = rem & (W_O - 1);

    const int coutg = tid & 15;         // 16 groups of 4 couts
    const int pxg   = tid >> 4;         // 16 groups of 8 px
    const int c0    = coutg * 4;
    const int px0   = pxg * 8;

    // acc[cp][j]: lanes = couts (c0+2cp, c0+2cp+1) for pixel px0+j
    u64 acc[2][8];
    {
        const float b0 = __ldg(bias + c0 + 0);
        const float b1 = __ldg(bias + c0 + 1);
        const float b2 = __ldg(bias + c0 + 2);
        const float b3 = __ldg(bias + c0 + 3);
        const u64 p01 = pack2(b0, b1);
        const u64 p23 = pack2(b2, b3);
#pragma unroll
        for (int j = 0; j < 8; j++) { acc[0][j] = p01; acc[1][j] = p23; }
    }

    const float* offb = offset + (size_t)b * 2 * KK * HWO + ho * W_O + wo0;
    const float* xtb  = g_xt + (size_t)b * HW * C_IN;

    for (int k = 0; k < KK; k++) {
        __syncthreads();   // previous iteration's S/Wsh readers done

        // stage this k's weight tile: Wsh[cin][cout] (coalesced float4 copy)
        {
            const float4* src = (const float4*)(g_wt + k * (C_IN * C_OUT));
            float4* dst = (float4*)Wsh;
#pragma unroll
            for (int i = tid; i < 1024; i += TPB) dst[i] = src[i];
        }

        // per-pixel bilinear params -> smem (threads 0..127)
        if (tid < TPX) {
            const float offy = __ldg(offb + (2 * k + 0) * HWO + tid);
            const float offx = __ldg(offb + (2 * k + 1) * HWO + tid);
            const float py = (float)(ho - 1 + k / 3) + offy;
            const float px = (float)(wo0 + tid - 1 + k % 3) + offx;
            const float y0f = floorf(py);
            const float x0f = floorf(px);
            const int   y0  = (int)y0f;
            const int   x0  = (int)x0f;
            const float wy  = py - y0f;
            const float wx  = px - x0f;
            const int   y1  = y0 + 1;
            const int   x1  = x0 + 1;
            const bool vy0 = (y0 >= 0) && (y0 < H_IN);
            const bool vy1 = (y1 >= 0) && (y1 < H_IN);
            const bool vx0 = (x0 >= 0) && (x0 < W_IN);
            const bool vx1 = (x1 >= 0) && (x1 < W_IN);
            const int cy0 = min(max(y0, 0), H_IN - 1);
            const int cy1 = min(max(y1, 0), H_IN - 1);
            const int cx0 = min(max(x0, 0), W_IN - 1);
            const int cx1 = min(max(x1, 0), W_IN - 1);
            Pi[0 * TPX + tid] = cy0 * W_IN + cx0;
            Pi[1 * TPX + tid] = cy0 * W_IN + cx1;
            Pi[2 * TPX + tid] = cy1 * W_IN + cx0;
            Pi[3 * TPX + tid] = cy1 * W_IN + cx1;
            Pa[0 * TPX + tid] = (vy0 && vx0) ? (1.0f - wy) * (1.0f - wx) : 0.0f;
            Pa[1 * TPX + tid] = (vy0 && vx1) ? (1.0f - wy) * wx          : 0.0f;
            Pa[2 * TPX + tid] = (vy1 && vx0) ? wy * (1.0f - wx)          : 0.0f;
            Pa[3 * TPX + tid] = (vy1 && vx1) ? wy * wx                   : 0.0f;
        }
        __syncthreads();

        // fill S[px][cin]: 2048 float4 units, 8 per thread.
        // lane mapping: cg = consecutive lanes -> coalesced LDG.128 from NHWC x
#pragma unroll
        for (int i = 0; i < 8; i++) {
            const int u  = tid + TPB * i;
            const int cg = u & 15;       // channel group (4 channels)
            const int px = u >> 4;       // pixel in tile
            const int i00 = Pi[0 * TPX + px];
            const int i01 = Pi[1 * TPX + px];
            const int i10 = Pi[2 * TPX + px];
            const int i11 = Pi[3 * TPX + px];
            const float a00 = Pa[0 * TPX + px];
            const float a01 = Pa[1 * TPX + px];
            const float a10 = Pa[2 * TPX + px];
            const float a11 = Pa[3 * TPX + px];
            const float4 v00 = __ldg((const float4*)(xtb + (size_t)i00 * C_IN) + cg);
            const float4 v01 = __ldg((const float4*)(xtb + (size_t)i01 * C_IN) + cg);
            const float4 v10 = __ldg((const float4*)(xtb + (size_t)i10 * C_IN) + cg);
            const float4 v11 = __ldg((const float4*)(xtb + (size_t)i11 * C_IN) + cg);
            float4 r;
            r.x = fmaf(v00.x, a00, fmaf(v01.x, a01, fmaf(v10.x, a10, v11.x * a11)));
            r.y = fmaf(v00.y, a00, fmaf(v01.y, a01, fmaf(v10.y, a10, v11.y * a11)));
            r.z = fmaf(v00.z, a00, fmaf(v01.z, a01, fmaf(v10.z, a10, v11.z * a11)));
            r.w = fmaf(v00.w, a00, fmaf(v01.w, a01, fmaf(v10.w, a10, v11.w * a11)));
            *(float4*)(S + px * SROW + cg * 4) = r;
        }
        __syncthreads();

        // GEMM: acc[cout 4][px 8] += W[cin][cout] * S[px][cin]
#pragma unroll 4
        for (int cin = 0; cin < C_IN; cin++) {
            const ulonglong2 wv = *(const ulonglong2*)(Wsh + cin * C_OUT + c0); // LDS.128
            const float* srow = S + px0 * SROW + cin;
#pragma unroll
            for (int j = 0; j < 8; j++) {
                const float sv = srow[j * SROW];       // broadcast LDS.32
                const u64 s2 = pack2(sv, sv);
                acc[0][j] = fma2(wv.x, s2, acc[0][j]);
                acc[1][j] = fma2(wv.y, s2, acc[1][j]);
            }
        }
    }

    // epilogue: out[b][cout][ho][wo], vectorized float4 along px
    float* ob = out + (size_t)b * C_OUT * HWO + ho * W_O + wo0 + px0;
#pragma unroll
    for (int cp = 0; cp < 2; cp++) {
        float lo[8], hi[8];
#pragma unroll
        for (int j = 0; j < 8; j++) unpack2(acc[cp][j], lo[j], hi[j]);
        float* r0 = ob + (size_t)(c0 + 2 * cp + 0) * HWO;
        float* r1 = ob + (size_t)(c0 + 2 * cp + 1) * HWO;
        ((float4*)r0)[0] = make_float4(lo[0], lo[1], lo[2], lo[3]);
        ((float4*)r0)[1] = make_float4(lo[4], lo[5], lo[6], lo[7]);
        ((float4*)r1)[0] = make_float4(hi[0], hi[1], hi[2], hi[3]);
        ((float4*)r1)[1] = make_float4(hi[4], hi[5], hi[6], hi[7]);
    }
}

extern "C" void kernel_launch(void* const* d_in, const int* in_sizes, int n_in,
                              void* d_out, int out_size) {
    const float* x      = (const float*)d_in[0];
    const float* offset = (const float*)d_in[1];
    const float* weight = (const float*)d_in[2];
    const float* bias   = (const float*)d_in[3];
    float* out = (float*)d_out;
    (void)in_sizes; (void)n_in; (void)out_size;

    // idempotent; safe during capture (no stream work enqueued)
    cudaFuncSetAttribute(deform_main,
                         cudaFuncAttributeMaxDynamicSharedMemorySize, SMEM_BYTES);

    dim3 tg(HW / 32, C_IN / 32, B_N);
    transpose_nchw_nhwc<<<tg, dim3(32, 8)>>>(x);
    transpose_weight<<<(KK * C_IN * C_OUT + 255) / 256, 256>>>(weight);
    deform_main<<<NPIX / TPX, TPB, SMEM_BYTES>>>(offset, bias, out);
}